// round 2
// baseline (speedup 1.0000x reference)
#include <cuda_runtime.h>
#include <math.h>

#define B_  2
#define S_  1024
#define D_  1024
#define H_  16
#define DH_ 64
#define M_  (B_*S_)
#define EPSF 1e-5f

// ---- scratch (static device globals; no allocation) ----
__device__ float g_qh [B_*H_*S_*DH_];   // 8 MB  [bh][s][d]  exp-mapped q
__device__ float g_kh [B_*H_*S_*DH_];   // 8 MB
__device__ float g_vt [B_*H_*S_*DH_];   // 8 MB  v_tan = log_map(exp_map(v))
__device__ float g_qns[B_*H_*S_];       // ||q_h||^2 per row
__device__ float g_kns[B_*H_*S_];
__device__ float g_att[B_*S_*D_];       // 8 MB  concat-layout attention output (head-transformed)

__device__ __forceinline__ float softplusf(float x){ return log1pf(expf(x)); }

// ======================================================================
// QKV GEMM:  Y = X @ W^T  (X [2048,1024], W [1024,1024] row-major)
// BM=128, BN=64 (== one head), BK=16, 256 threads, thread tile 8x4.
// Epilogue fuses exp_map (z=0,1 -> also store ||.||^2) or exp∘log (z=2).
// ======================================================================
__global__ __launch_bounds__(256) void qkv_gemm(
    const float* __restrict__ X,
    const float* __restrict__ Wq,
    const float* __restrict__ Wk,
    const float* __restrict__ Wv,
    const float* __restrict__ log_c_p)
{
    __shared__ float As[16*132];   // [kk][m], padded
    __shared__ float Bs[16*68];    // [kk][n], padded

    const int z   = blockIdx.z;
    const float* __restrict__ W = (z==0) ? Wq : ((z==1) ? Wk : Wv);
    const int m0 = blockIdx.y * 128;
    const int n0 = blockIdx.x * 64;
    const int tid = threadIdx.x;
    const int tx = tid & 15, ty = tid >> 4;

    float acc[8][4];
    #pragma unroll
    for (int i=0;i<8;++i)
        #pragma unroll
        for (int j=0;j<4;++j) acc[i][j] = 0.f;

    const float4* __restrict__ X4 = reinterpret_cast<const float4*>(X);
    const float4* __restrict__ W4 = reinterpret_cast<const float4*>(W);

    for (int kt = 0; kt < 64; ++kt) {
        // load A tile 128x16  (512 float4, 2 per thread)
        #pragma unroll
        for (int u = 0; u < 2; ++u) {
            int idx = tid + u*256;
            int row = idx >> 2, kq = idx & 3;
            float4 v = X4[(size_t)(m0+row)*256 + kt*4 + kq];
            As[(kq*4+0)*132 + row] = v.x;
            As[(kq*4+1)*132 + row] = v.y;
            As[(kq*4+2)*132 + row] = v.z;
            As[(kq*4+3)*132 + row] = v.w;
        }
        // load B tile 64x16   (256 float4, 1 per thread)
        {
            int row = tid >> 2, kq = tid & 3;
            float4 v = W4[(size_t)(n0+row)*256 + kt*4 + kq];
            Bs[(kq*4+0)*68 + row] = v.x;
            Bs[(kq*4+1)*68 + row] = v.y;
            Bs[(kq*4+2)*68 + row] = v.z;
            Bs[(kq*4+3)*68 + row] = v.w;
        }
        __syncthreads();
        #pragma unroll
        for (int kk = 0; kk < 16; ++kk) {
            float4 a0 = *reinterpret_cast<const float4*>(&As[kk*132 + ty*8]);
            float4 a1 = *reinterpret_cast<const float4*>(&As[kk*132 + ty*8 + 4]);
            float4 b0 = *reinterpret_cast<const float4*>(&Bs[kk*68 + tx*4]);
            float av[8] = {a0.x,a0.y,a0.z,a0.w,a1.x,a1.y,a1.z,a1.w};
            float bv[4] = {b0.x,b0.y,b0.z,b0.w};
            #pragma unroll
            for (int i=0;i<8;++i)
                #pragma unroll
                for (int j=0;j<4;++j)
                    acc[i][j] = fmaf(av[i], bv[j], acc[i][j]);
        }
        __syncthreads();
    }

    // ---- epilogue: hyperbolic maps per head-row (BN=64 == one head) ----
    const float c_  = softplusf(*log_c_p);
    const float sc  = sqrtf(c_);
    const float inv_sc = 1.0f / sc;
    const int h = blockIdx.x;            // n0/64
    float* __restrict__ outp = (z==0) ? g_qh : ((z==1) ? g_kh : g_vt);
    float* __restrict__ nsp  = (z==0) ? g_qns : g_kns;

    #pragma unroll
    for (int i = 0; i < 8; ++i) {
        int m = m0 + ty*8 + i;
        int b = m >> 10, s = m & 1023;
        float ss = acc[i][0]*acc[i][0] + acc[i][1]*acc[i][1]
                 + acc[i][2]*acc[i][2] + acc[i][3]*acc[i][3];
        ss += __shfl_xor_sync(0xffffffffu, ss, 1);
        ss += __shfl_xor_sync(0xffffffffu, ss, 2);
        ss += __shfl_xor_sync(0xffffffffu, ss, 4);
        ss += __shfl_xor_sync(0xffffffffu, ss, 8);
        float n   = fmaxf(sqrtf(ss), EPSF);
        float scn = sc * n;
        float t1  = tanhf(scn);
        float scale;
        if (z < 2) {
            scale = t1 / scn;                         // exp_map
        } else {
            // log_map(exp_map(v)): identity unless clamped
            float thresh = 1.0f - sc*EPSF;            // sc*(inv_sc - EPS)
            if (t1 < thresh) scale = 1.0f;
            else             scale = atanhf(thresh) / scn;
        }
        float e0 = scale*acc[i][0], e1 = scale*acc[i][1];
        float e2 = scale*acc[i][2], e3 = scale*acc[i][3];
        int base = ((b*H_ + h)*S_ + s)*DH_ + tx*4;
        outp[base+0]=e0; outp[base+1]=e1; outp[base+2]=e2; outp[base+3]=e3;
        if (z < 2) {
            float s2 = e0*e0 + e1*e1 + e2*e2 + e3*e3;
            s2 += __shfl_xor_sync(0xffffffffu, s2, 1);
            s2 += __shfl_xor_sync(0xffffffffu, s2, 2);
            s2 += __shfl_xor_sync(0xffffffffu, s2, 4);
            s2 += __shfl_xor_sync(0xffffffffu, s2, 8);
            if (tx == 0) nsp[(b*H_ + h)*S_ + s] = s2;
        }
    }
}

// ======================================================================
// Attention: per (bh, 64-query block). Flash-style over 16 key tiles.
// smem layout (floats):
//   Qs 64x68 | Ks 64x65 | Vs 64x68 | Ps 64x65 | qns 64 | omx 64 |
//   kns 64 | omy 64 | mrow 64 | lrow 64 | corr 64 | red 256
// ======================================================================
#define QS_OFF   0
#define KS_OFF   (64*68)
#define VS_OFF   (KS_OFF + 64*65)
#define PS_OFF   (VS_OFF + 64*68)
#define QNS_OFF  (PS_OFF + 64*65)
#define OMX_OFF  (QNS_OFF + 64)
#define KNS_OFF  (OMX_OFF + 64)
#define OMY_OFF  (KNS_OFF + 64)
#define MR_OFF   (OMY_OFF + 64)
#define LR_OFF   (MR_OFF + 64)
#define CR_OFF   (LR_OFF + 64)
#define RED_OFF  (CR_OFF + 64)
#define ATTN_SMEM_FLOATS (RED_OFF + 256)
#define ATTN_SMEM_BYTES  (ATTN_SMEM_FLOATS * 4)

__global__ __launch_bounds__(256) void attn_kernel(
    const float* __restrict__ log_c_p,
    const float* __restrict__ beta_p,
    const float* __restrict__ bias_p)
{
    extern __shared__ float sm[];
    float* Qs  = sm + QS_OFF;
    float* Ks  = sm + KS_OFF;
    float* Vs  = sm + VS_OFF;
    float* Ps  = sm + PS_OFF;
    float* qns = sm + QNS_OFF;
    float* omx = sm + OMX_OFF;
    float* kns = sm + KNS_OFF;
    float* omy = sm + OMY_OFF;
    float* mrow= sm + MR_OFF;
    float* lrow= sm + LR_OFF;
    float* corr= sm + CR_OFF;
    float* red = sm + RED_OFF;

    const int bh = blockIdx.y;                 // 0..31
    const int q0 = blockIdx.x * 64;
    const int tid = threadIdx.x;
    const int tx = tid & 15, ty = tid >> 4;

    const float c_  = softplusf(*log_c_p);
    const float sc  = sqrtf(c_);
    const float inv_sc = 1.0f / sc;
    const float beta_pos = softplusf(*beta_p);
    const float bias = *bias_p;
    const float bis  = beta_pos * inv_sc;

    const float* __restrict__ Qg = g_qh + (size_t)bh*S_*DH_;
    const float* __restrict__ Kg = g_kh + (size_t)bh*S_*DH_;
    const float* __restrict__ Vg = g_vt + (size_t)bh*S_*DH_;

    // load Q tile + per-row stats
    #pragma unroll
    for (int u = 0; u < 4; ++u) {
        int idx = tid + u*256;
        int r = idx >> 4, c4 = idx & 15;
        float4 v = *reinterpret_cast<const float4*>(&Qg[(q0+r)*DH_ + c4*4]);
        *reinterpret_cast<float4*>(&Qs[r*68 + c4*4]) = v;
    }
    if (tid < 64) {
        float qn = g_qns[bh*S_ + q0 + tid];
        qns[tid] = qn;
        omx[tid] = __fsub_rn(1.0f, __fmul_rn(c_, qn));
        mrow[tid] = -INFINITY;
        lrow[tid] = 0.0f;
    }
    __syncthreads();

    float o[4][4];
    #pragma unroll
    for (int i=0;i<4;++i)
        #pragma unroll
        for (int j=0;j<4;++j) o[i][j]=0.f;

    for (int kt = 0; kt < 16; ++kt) {
        const int k0 = kt * 64;
        #pragma unroll
        for (int u = 0; u < 4; ++u) {
            int idx = tid + u*256;
            int r = idx >> 4, c4 = idx & 15;
            float4 kv = *reinterpret_cast<const float4*>(&Kg[(k0+r)*DH_ + c4*4]);
            Ks[r*65 + c4*4+0]=kv.x; Ks[r*65 + c4*4+1]=kv.y;
            Ks[r*65 + c4*4+2]=kv.z; Ks[r*65 + c4*4+3]=kv.w;
            float4 vv = *reinterpret_cast<const float4*>(&Vg[(k0+r)*DH_ + c4*4]);
            *reinterpret_cast<float4*>(&Vs[r*68 + c4*4]) = vv;
        }
        if (tid < 64) {
            float kn = g_kns[bh*S_ + k0 + tid];
            kns[tid] = kn;
            omy[tid] = __fsub_rn(1.0f, __fmul_rn(c_, kn));
        }
        __syncthreads();

        // ---- S = Q K^T (64x64x64) ----
        float s[4][4];
        #pragma unroll
        for (int i=0;i<4;++i)
            #pragma unroll
            for (int j=0;j<4;++j) s[i][j]=0.f;

        #pragma unroll 8
        for (int d = 0; d < 64; ++d) {
            float a0 = Qs[(ty*4+0)*68 + d];
            float a1 = Qs[(ty*4+1)*68 + d];
            float a2 = Qs[(ty*4+2)*68 + d];
            float a3 = Qs[(ty*4+3)*68 + d];
            float b0 = Ks[(tx*4+0)*65 + d];
            float b1 = Ks[(tx*4+1)*65 + d];
            float b2 = Ks[(tx*4+2)*65 + d];
            float b3 = Ks[(tx*4+3)*65 + d];
            s[0][0]=fmaf(a0,b0,s[0][0]); s[0][1]=fmaf(a0,b1,s[0][1]);
            s[0][2]=fmaf(a0,b2,s[0][2]); s[0][3]=fmaf(a0,b3,s[0][3]);
            s[1][0]=fmaf(a1,b0,s[1][0]); s[1][1]=fmaf(a1,b1,s[1][1]);
            s[1][2]=fmaf(a1,b2,s[1][2]); s[1][3]=fmaf(a1,b3,s[1][3]);
            s[2][0]=fmaf(a2,b0,s[2][0]); s[2][1]=fmaf(a2,b1,s[2][1]);
            s[2][2]=fmaf(a2,b2,s[2][2]); s[2][3]=fmaf(a2,b3,s[2][3]);
            s[3][0]=fmaf(a3,b0,s[3][0]); s[3][1]=fmaf(a3,b1,s[3][1]);
            s[3][2]=fmaf(a3,b2,s[3][2]); s[3][3]=fmaf(a3,b3,s[3][3]);
        }

        // ---- Poincare distance -> raw scores into Ps[t][r] ----
        #pragma unroll
        for (int i=0;i<4;++i) {
            int r = ty*4+i;
            float qn = qns[r], ox = omx[r];
            #pragma unroll
            for (int j=0;j<4;++j) {
                int t = tx*4+j;
                float dsq   = qn - 2.0f*s[i][j] + kns[t];
                float denom = fmaxf(ox*omy[t], EPSF);
                float arg   = 1.0f + __fdividef(2.0f*c_*dsq, denom);
                arg = fmaxf(arg, 1.0f + EPSF);
                float dist = acoshf(arg);
                Ps[t*65 + r] = fmaf(-bis, dist, -bias);
            }
        }
        __syncthreads();

        // ---- online softmax (4 threads per row) ----
        const int rr = tid >> 2, part = tid & 3;
        float lmax = -INFINITY;
        #pragma unroll
        for (int k=0;k<16;++k) lmax = fmaxf(lmax, Ps[(part*16+k)*65 + rr]);
        red[rr*4+part] = lmax;
        __syncthreads();
        if (part == 0) {
            float tm = fmaxf(fmaxf(red[rr*4],red[rr*4+1]),fmaxf(red[rr*4+2],red[rr*4+3]));
            float mo = mrow[rr];
            float mn = fmaxf(mo, tm);
            mrow[rr] = mn;
            corr[rr] = expf(mo - mn);
        }
        __syncthreads();
        {
            float msv = mrow[rr];
            float lsum = 0.f;
            #pragma unroll
            for (int k=0;k<16;++k) {
                int t = part*16+k;
                float p = expf(Ps[t*65+rr] - msv);
                Ps[t*65+rr] = p;
                lsum += p;
            }
            red[rr*4+part] = lsum;
        }
        __syncthreads();
        if (part == 0)
            lrow[rr] = lrow[rr]*corr[rr] + red[rr*4]+red[rr*4+1]+red[rr*4+2]+red[rr*4+3];

        // rescale O accum
        #pragma unroll
        for (int i=0;i<4;++i) {
            float cr = corr[ty*4+i];
            #pragma unroll
            for (int j=0;j<4;++j) o[i][j] *= cr;
        }
        // ---- O += P V ----
        #pragma unroll 4
        for (int t=0;t<64;++t) {
            float p0 = Ps[t*65 + ty*4+0];
            float p1 = Ps[t*65 + ty*4+1];
            float p2 = Ps[t*65 + ty*4+2];
            float p3 = Ps[t*65 + ty*4+3];
            float4 v4 = *reinterpret_cast<const float4*>(&Vs[t*68 + tx*4]);
            o[0][0]=fmaf(p0,v4.x,o[0][0]); o[0][1]=fmaf(p0,v4.y,o[0][1]);
            o[0][2]=fmaf(p0,v4.z,o[0][2]); o[0][3]=fmaf(p0,v4.w,o[0][3]);
            o[1][0]=fmaf(p1,v4.x,o[1][0]); o[1][1]=fmaf(p1,v4.y,o[1][1]);
            o[1][2]=fmaf(p1,v4.z,o[1][2]); o[1][3]=fmaf(p1,v4.w,o[1][3]);
            o[2][0]=fmaf(p2,v4.x,o[2][0]); o[2][1]=fmaf(p2,v4.y,o[2][1]);
            o[2][2]=fmaf(p2,v4.z,o[2][2]); o[2][3]=fmaf(p2,v4.w,o[2][3]);
            o[3][0]=fmaf(p3,v4.x,o[3][0]); o[3][1]=fmaf(p3,v4.y,o[3][1]);
            o[3][2]=fmaf(p3,v4.z,o[3][2]); o[3][3]=fmaf(p3,v4.w,o[3][3]);
        }
        __syncthreads();
    }

    // ---- finalize: /l, then log_map(exp_map(.)) per head row, write concat ----
    const int b = bh >> 4, h = bh & 15;
    #pragma unroll
    for (int i=0;i<4;++i) {
        int r = ty*4+i;
        float invl = 1.0f / lrow[r];
        float e0 = o[i][0]*invl, e1 = o[i][1]*invl;
        float e2 = o[i][2]*invl, e3 = o[i][3]*invl;
        float ss = e0*e0 + e1*e1 + e2*e2 + e3*e3;
        ss += __shfl_xor_sync(0xffffffffu, ss, 1);
        ss += __shfl_xor_sync(0xffffffffu, ss, 2);
        ss += __shfl_xor_sync(0xffffffffu, ss, 4);
        ss += __shfl_xor_sync(0xffffffffu, ss, 8);
        float n   = fmaxf(sqrtf(ss), EPSF);
        float scn = sc * n;
        float t1  = tanhf(scn);
        float thresh = 1.0f - sc*EPSF;
        float scale = (t1 < thresh) ? 1.0f : (atanhf(thresh) / scn);
        int dst = (b*S_ + q0 + r)*D_ + h*DH_ + tx*4;
        g_att[dst+0] = e0*scale;
        g_att[dst+1] = e1*scale;
        g_att[dst+2] = e2*scale;
        g_att[dst+3] = e3*scale;
    }
}

// ======================================================================
// Output GEMM: out = g_att @ Wo^T   (plain epilogue)
// ======================================================================
__global__ __launch_bounds__(256) void out_gemm(
    const float* __restrict__ Wo, float* __restrict__ C)
{
    __shared__ float As[16*132];
    __shared__ float Bs[16*68];

    const int m0 = blockIdx.y * 128;
    const int n0 = blockIdx.x * 64;
    const int tid = threadIdx.x;
    const int tx = tid & 15, ty = tid >> 4;

    float acc[8][4];
    #pragma unroll
    for (int i=0;i<8;++i)
        #pragma unroll
        for (int j=0;j<4;++j) acc[i][j]=0.f;

    const float4* __restrict__ A4 = reinterpret_cast<const float4*>(g_att);
    const float4* __restrict__ W4 = reinterpret_cast<const float4*>(Wo);

    for (int kt = 0; kt < 64; ++kt) {
        #pragma unroll
        for (int u = 0; u < 2; ++u) {
            int idx = tid + u*256;
            int row = idx >> 2, kq = idx & 3;
            float4 v = A4[(size_t)(m0+row)*256 + kt*4 + kq];
            As[(kq*4+0)*132 + row] = v.x;
            As[(kq*4+1)*132 + row] = v.y;
            As[(kq*4+2)*132 + row] = v.z;
            As[(kq*4+3)*132 + row] = v.w;
        }
        {
            int row = tid >> 2, kq = tid & 3;
            float4 v = W4[(size_t)(n0+row)*256 + kt*4 + kq];
            Bs[(kq*4+0)*68 + row] = v.x;
            Bs[(kq*4+1)*68 + row] = v.y;
            Bs[(kq*4+2)*68 + row] = v.z;
            Bs[(kq*4+3)*68 + row] = v.w;
        }
        __syncthreads();
        #pragma unroll
        for (int kk = 0; kk < 16; ++kk) {
            float4 a0 = *reinterpret_cast<const float4*>(&As[kk*132 + ty*8]);
            float4 a1 = *reinterpret_cast<const float4*>(&As[kk*132 + ty*8 + 4]);
            float4 b0 = *reinterpret_cast<const float4*>(&Bs[kk*68 + tx*4]);
            float av[8] = {a0.x,a0.y,a0.z,a0.w,a1.x,a1.y,a1.z,a1.w};
            float bv[4] = {b0.x,b0.y,b0.z,b0.w};
            #pragma unroll
            for (int i=0;i<8;++i)
                #pragma unroll
                for (int j=0;j<4;++j)
                    acc[i][j] = fmaf(av[i], bv[j], acc[i][j]);
        }
        __syncthreads();
    }
    #pragma unroll
    for (int i=0;i<8;++i) {
        int m = m0 + ty*8 + i;
        int base = m*D_ + n0 + tx*4;
        C[base+0]=acc[i][0]; C[base+1]=acc[i][1];
        C[base+2]=acc[i][2]; C[base+3]=acc[i][3];
    }
}

// ======================================================================
extern "C" void kernel_launch(void* const* d_in, const int* in_sizes, int n_in,
                              void* d_out, int out_size)
{
    (void)in_sizes; (void)n_in; (void)out_size;
    const float* x    = (const float*)d_in[0];
    const float* Wq   = (const float*)d_in[1];
    const float* Wk   = (const float*)d_in[2];
    const float* Wv   = (const float*)d_in[3];
    const float* Wo   = (const float*)d_in[4];
    const float* logc = (const float*)d_in[5];
    const float* beta = (const float*)d_in[6];
    const float* bias = (const float*)d_in[7];
    float* out = (float*)d_out;

    cudaFuncSetAttribute(attn_kernel,
                         cudaFuncAttributeMaxDynamicSharedMemorySize,
                         ATTN_SMEM_BYTES);

    qkv_gemm<<<dim3(16,16,3), 256>>>(x, Wq, Wk, Wv, logc);
    attn_kernel<<<dim3(16,32), 256, ATTN_SMEM_BYTES>>>(logc, beta, bias);
    out_gemm<<<dim3(16,16), 256>>>(Wo, out);
}